// round 16
// baseline (speedup 1.0000x reference)
#include <cuda_runtime.h>
#include <math.h>

#define NN 100000
#define EE 1600000
#define DD 128
#define NB 391   // ceil(NN/256)

// ---- scratch (allocation-free: device globals) ----
__device__ __align__(16) int   g_deg[NN];
__device__ __align__(16) int   g_cursor[NN];
__device__ __align__(16) int   g_rowstart[NN];
__device__ __align__(16) int   g_bsum[512];
__device__ __align__(16) int   g_boff[512];
__device__ int                 g_w64;               // 1 if edge_index is int64
__device__ __align__(16) float g_dis[NN];
__device__ __align__(16) int2  g_epack[EE];         // {src, coef bits}
__device__ __align__(16) float g_xw [(size_t)NN * DD];
__device__ __align__(16) float g_agg[(size_t)NN * DD];

// ---------------------------------------------------------------------------
// dtype probe: if edge_index is int64 (little-endian, values < 2^31), every
// odd 32-bit word is 0. If int32, odd words are node ids (~all nonzero).
// ---------------------------------------------------------------------------
__global__ void k_detect(const int* __restrict__ ei32) {
    __shared__ int nz;
    if (threadIdx.x == 0) nz = 0;
    __syncthreads();
    for (int i = threadIdx.x; i < 4096; i += 256)
        if (ei32[2 * i + 1] != 0) atomicOr(&nz, 1);
    __syncthreads();
    if (threadIdx.x == 0) g_w64 = (nz == 0) ? 1 : 0;
}

// ---------------------------------------------------------------------------
// degree / normalization / CSR build (index loads are dtype-agnostic)
// ---------------------------------------------------------------------------
__global__ void k_zero() {
    int i = blockIdx.x * blockDim.x + threadIdx.x;
    if (i < NN) { g_deg[i] = 0; g_cursor[i] = 0; }
}

__global__ void k_deg(const int* __restrict__ ei32) {
    int e = blockIdx.x * blockDim.x + threadIdx.x;
    if (e >= EE) return;
    int w64 = g_w64;
    size_t di = w64 ? (2 * (size_t)EE + 2 * (size_t)e) : ((size_t)EE + e);
    unsigned d = (unsigned)ei32[di];
    if (d < NN) atomicAdd(&g_deg[d], 1);
}

__global__ void k_dis() {
    int i = blockIdx.x * blockDim.x + threadIdx.x;
    if (i < NN) g_dis[i] = rsqrtf((float)g_deg[i] + 1.0f);
}

// pass 1: per-block inclusive scan -> exclusive rowstart (partial) + block sums
__global__ __launch_bounds__(256) void k_scan1() {
    __shared__ int s[256];
    int t = threadIdx.x, b = blockIdx.x;
    int i = b * 256 + t;
    int v = (i < NN) ? g_deg[i] : 0;
    s[t] = v; __syncthreads();
#pragma unroll
    for (int off = 1; off < 256; off <<= 1) {
        int x = 0;
        if (t >= off) x = s[t - off];
        __syncthreads();
        s[t] += x;
        __syncthreads();
    }
    if (i < NN) g_rowstart[i] = s[t] - v;
    if (t == 255) g_bsum[b] = s[255];
}

// pass 2: single block scans the NB block sums (exclusive)
__global__ __launch_bounds__(512) void k_scan2() {
    __shared__ int s[512];
    int t = threadIdx.x;
    int v = (t < NB) ? g_bsum[t] : 0;
    s[t] = v; __syncthreads();
#pragma unroll
    for (int off = 1; off < 512; off <<= 1) {
        int x = 0;
        if (t >= off) x = s[t - off];
        __syncthreads();
        s[t] += x;
        __syncthreads();
    }
    if (t < NB) g_boff[t] = s[t] - v;
}

// pass 3: add block offsets
__global__ __launch_bounds__(256) void k_scan3() {
    int i = blockIdx.x * 256 + threadIdx.x;
    if (i < NN) g_rowstart[i] += g_boff[blockIdx.x];
}

// bucket edges by dst: epack[slot] = {src, bits(dis[src]*dis[dst])}
__global__ void k_bucket(const int* __restrict__ ei32) {
    int e = blockIdx.x * blockDim.x + threadIdx.x;
    if (e >= EE) return;
    int w64 = g_w64;
    size_t si = w64 ? (2 * (size_t)e) : (size_t)e;
    size_t di = w64 ? (2 * (size_t)EE + 2 * (size_t)e) : ((size_t)EE + e);
    unsigned s = (unsigned)ei32[si];
    unsigned d = (unsigned)ei32[di];
    if (s >= NN || d >= NN) return;                 // clamp: drop bad edge
    int pos = g_rowstart[d] + atomicAdd(&g_cursor[d], 1);
    if ((unsigned)pos >= EE) return;                // clamp: cannot fault
    int2 q;
    q.x = (int)s;
    q.y = __float_as_int(g_dis[s] * g_dis[d]);
    g_epack[pos] = q;
}

// ---------------------------------------------------------------------------
// GEMM: C[64 x 128] tile per block, K=128 in 4 chunks of 32.
// epi_conv == 1: out_xw = A@W ; out_agg = dis^2 * (A@W) + bias   (pre-gather)
// epi_conv == 0: out_xw = relu(A@W + bias)                        (projections)
// relu_in  == 1: relu applied to A on load (fuses layer-1 activation)
// ---------------------------------------------------------------------------
__global__ __launch_bounds__(256) void k_gemm(
    const float* __restrict__ A, const float* __restrict__ W,
    const float* __restrict__ bias,
    float* __restrict__ out_xw, float* __restrict__ out_agg,
    int relu_in, int epi_conv)
{
    __shared__ float4 As[64 * 8];   // 64 rows x 32 k
    __shared__ float4 Ws[32 * 32];  // 32 k x 128 cols

    const int tid = threadIdx.x;
    const int tx  = tid & 31;
    const int ty  = tid >> 5;
    const int rowBase = blockIdx.x * 64;

    const float4* A4 = (const float4*)A;
    const float4* W4 = (const float4*)W;

    float4 acc[8];
#pragma unroll
    for (int i = 0; i < 8; i++) acc[i] = make_float4(0.f, 0.f, 0.f, 0.f);

    for (int kc = 0; kc < DD; kc += 32) {
        for (int t = tid; t < 64 * 8; t += 256) {
            int r = t >> 3, c = t & 7;
            int rg = rowBase + r;
            float4 v = make_float4(0.f, 0.f, 0.f, 0.f);
            if (rg < NN) v = A4[(size_t)rg * 32 + (kc >> 2) + c];
            if (relu_in) {
                v.x = fmaxf(v.x, 0.f); v.y = fmaxf(v.y, 0.f);
                v.z = fmaxf(v.z, 0.f); v.w = fmaxf(v.w, 0.f);
            }
            As[t] = v;
        }
        for (int t = tid; t < 32 * 32; t += 256) {
            int k = t >> 5, c = t & 31;
            Ws[t] = W4[(size_t)(kc + k) * 32 + c];
        }
        __syncthreads();

#pragma unroll
        for (int k4 = 0; k4 < 8; k4++) {
            float4 b0 = Ws[(k4 * 4 + 0) * 32 + tx];
            float4 b1 = Ws[(k4 * 4 + 1) * 32 + tx];
            float4 b2 = Ws[(k4 * 4 + 2) * 32 + tx];
            float4 b3 = Ws[(k4 * 4 + 3) * 32 + tx];
#pragma unroll
            for (int i = 0; i < 8; i++) {
                float4 a = As[(ty * 8 + i) * 8 + k4];
                acc[i].x = fmaf(a.x, b0.x, acc[i].x);
                acc[i].x = fmaf(a.y, b1.x, acc[i].x);
                acc[i].x = fmaf(a.z, b2.x, acc[i].x);
                acc[i].x = fmaf(a.w, b3.x, acc[i].x);
                acc[i].y = fmaf(a.x, b0.y, acc[i].y);
                acc[i].y = fmaf(a.y, b1.y, acc[i].y);
                acc[i].y = fmaf(a.z, b2.y, acc[i].y);
                acc[i].y = fmaf(a.w, b3.y, acc[i].y);
                acc[i].z = fmaf(a.x, b0.z, acc[i].z);
                acc[i].z = fmaf(a.y, b1.z, acc[i].z);
                acc[i].z = fmaf(a.z, b2.z, acc[i].z);
                acc[i].z = fmaf(a.w, b3.z, acc[i].z);
                acc[i].w = fmaf(a.x, b0.w, acc[i].w);
                acc[i].w = fmaf(a.y, b1.w, acc[i].w);
                acc[i].w = fmaf(a.z, b2.w, acc[i].w);
                acc[i].w = fmaf(a.w, b3.w, acc[i].w);
            }
        }
        __syncthreads();
    }

    const float4 bv = ((const float4*)bias)[tx];
#pragma unroll
    for (int i = 0; i < 8; i++) {
        int rg = rowBase + ty * 8 + i;
        if (rg >= NN) continue;
        float4 o = acc[i];
        if (epi_conv) {
            ((float4*)out_xw)[(size_t)rg * 32 + tx] = o;
            float d = g_dis[rg];
            float d2 = d * d;
            float4 g;
            g.x = fmaf(o.x, d2, bv.x);
            g.y = fmaf(o.y, d2, bv.y);
            g.z = fmaf(o.z, d2, bv.z);
            g.w = fmaf(o.w, d2, bv.w);
            ((float4*)out_agg)[(size_t)rg * 32 + tx] = g;
        } else {
            float4 g;
            g.x = fmaxf(o.x + bv.x, 0.f);
            g.y = fmaxf(o.y + bv.y, 0.f);
            g.z = fmaxf(o.z + bv.z, 0.f);
            g.w = fmaxf(o.w + bv.w, 0.f);
            ((float4*)out_xw)[(size_t)rg * 32 + tx] = g;
        }
    }
}

// ---------------------------------------------------------------------------
// CSR gather: one warp per dst node, lane owns one float4 column chunk.
// acc starts from agg[dst] (= dis^2*xw + b from GEMM epilogue); no atomics.
// ---------------------------------------------------------------------------
__global__ __launch_bounds__(256) void k_gather(
    const float* __restrict__ xw, float* __restrict__ agg)
{
    int node = blockIdx.x * 8 + (threadIdx.x >> 5);
    int lane = threadIdx.x & 31;
    if (node >= NN) return;

    int start = g_rowstart[node];
    int cnt   = g_deg[node];
    start = max(0, min(start, EE));                 // clamp: cannot fault
    cnt   = max(0, min(cnt, EE - start));

    const int2*   ep  = g_epack + start;
    const float4* xw4 = (const float4*)xw;

    float4 acc = ((const float4*)agg)[(size_t)node * 32 + lane];

    int j = 0;
    for (; j + 4 <= cnt; j += 4) {
        int2 p0 = ep[j + 0];
        int2 p1 = ep[j + 1];
        int2 p2 = ep[j + 2];
        int2 p3 = ep[j + 3];
        int s0 = min(max(p0.x, 0), NN - 1);
        int s1 = min(max(p1.x, 0), NN - 1);
        int s2 = min(max(p2.x, 0), NN - 1);
        int s3 = min(max(p3.x, 0), NN - 1);
        float c0 = __int_as_float(p0.y);
        float c1 = __int_as_float(p1.y);
        float c2 = __int_as_float(p2.y);
        float c3 = __int_as_float(p3.y);
        float4 v0 = xw4[(size_t)s0 * 32 + lane];
        float4 v1 = xw4[(size_t)s1 * 32 + lane];
        float4 v2 = xw4[(size_t)s2 * 32 + lane];
        float4 v3 = xw4[(size_t)s3 * 32 + lane];
        acc.x = fmaf(c0, v0.x, acc.x); acc.y = fmaf(c0, v0.y, acc.y);
        acc.z = fmaf(c0, v0.z, acc.z); acc.w = fmaf(c0, v0.w, acc.w);
        acc.x = fmaf(c1, v1.x, acc.x); acc.y = fmaf(c1, v1.y, acc.y);
        acc.z = fmaf(c1, v1.z, acc.z); acc.w = fmaf(c1, v1.w, acc.w);
        acc.x = fmaf(c2, v2.x, acc.x); acc.y = fmaf(c2, v2.y, acc.y);
        acc.z = fmaf(c2, v2.z, acc.z); acc.w = fmaf(c2, v2.w, acc.w);
        acc.x = fmaf(c3, v3.x, acc.x); acc.y = fmaf(c3, v3.y, acc.y);
        acc.z = fmaf(c3, v3.z, acc.z); acc.w = fmaf(c3, v3.w, acc.w);
    }
    for (; j < cnt; j++) {
        int2 p = ep[j];
        int sj = min(max(p.x, 0), NN - 1);
        float cj = __int_as_float(p.y);
        float4 v = xw4[(size_t)sj * 32 + lane];
        acc.x = fmaf(cj, v.x, acc.x); acc.y = fmaf(cj, v.y, acc.y);
        acc.z = fmaf(cj, v.z, acc.z); acc.w = fmaf(cj, v.w, acc.w);
    }

    ((float4*)agg)[(size_t)node * 32 + lane] = acc;
}

// ---------------------------------------------------------------------------
extern "C" void kernel_launch(void* const* d_in, const int* in_sizes, int n_in,
                              void* d_out, int out_size)
{
    // --- size-based input resolution (robust to ordering surprises) ---
    const float* x  = nullptr;
    const int*   ei = nullptr;    // edge_index as raw 32-bit words
    const float* mats[4] = {nullptr, nullptr, nullptr, nullptr};
    const float* vecs[4] = {nullptr, nullptr, nullptr, nullptr};
    int nm = 0, nv = 0;
    for (int i = 0; i < n_in; i++) {
        int sz = in_sizes[i];
        if (sz == NN * DD)            x  = (const float*)d_in[i];
        else if (sz == 2 * EE)        ei = (const int*)d_in[i];
        else if (sz == DD * DD) { if (nm < 4) mats[nm++] = (const float*)d_in[i]; }
        else if (sz == DD)      { if (nv < 4) vecs[nv++] = (const float*)d_in[i]; }
    }
    if (!x)  x  = (const float*)d_in[0];
    if (!ei) ei = (const int*)d_in[1];
    if (nm < 4) { mats[0]=(const float*)d_in[2]; mats[1]=(const float*)d_in[4];
                  mats[2]=(const float*)d_in[6]; mats[3]=(const float*)d_in[8]; }
    if (nv < 4) { vecs[0]=(const float*)d_in[3]; vecs[1]=(const float*)d_in[5];
                  vecs[2]=(const float*)d_in[7]; vecs[3]=(const float*)d_in[9]; }
    const float *W1 = mats[0], *W2 = mats[1], *Wv = mats[2], *Wt = mats[3];
    const float *b1 = vecs[0], *b2 = vecs[1], *bv = vecs[2], *bt = vecs[3];

    float* out = (float*)d_out;
    float* h  = out;                       // [N, D]
    float* xv = out + (size_t)NN * DD;     // [N, D]
    float* xt = out + 2 * (size_t)NN * DD; // [N, D]

    float* xw  = nullptr;
    float* agg = nullptr;
    cudaGetSymbolAddress((void**)&xw,  g_xw);
    cudaGetSymbolAddress((void**)&agg, g_agg);

    const int TPB = 256;
    dim3 gN((NN + TPB - 1) / TPB);    // == NB blocks
    dim3 gE((EE + TPB - 1) / TPB);
    dim3 gG((NN + 63) / 64);
    dim3 gW((NN + 7) / 8);            // gather: 8 warps/block, warp per node

    // dtype probe + normalization + CSR build
    k_detect<<<1, 256>>>(ei);
    k_zero <<<gN, TPB>>>();
    k_deg  <<<gE, TPB>>>(ei);
    k_scan1<<<gN, TPB>>>();
    k_scan2<<<1, 512>>>();
    k_scan3<<<gN, TPB>>>();
    k_dis  <<<gN, TPB>>>();
    k_bucket<<<gE, TPB>>>(ei);

    // layer 1: xw = x@W1 ; agg = dis^2*xw + b1 ; gather adds neighbors
    k_gemm  <<<gG, TPB>>>(x, W1, b1, xw, agg, /*relu_in=*/0, /*epi_conv=*/1);
    k_gather<<<gW, TPB>>>(xw, agg);

    // layer 2: reads relu(agg1) fused on load; agg target is d_out h region
    k_gemm  <<<gG, TPB>>>(agg, W2, b2, xw, h, /*relu_in=*/1, /*epi_conv=*/1);
    k_gather<<<gW, TPB>>>(xw, h);

    // output projections
    k_gemm<<<gG, TPB>>>(h, Wv, bv, xv, nullptr, /*relu_in=*/0, /*epi_conv=*/0);
    k_gemm<<<gG, TPB>>>(h, Wt, bt, xt, nullptr, /*relu_in=*/0, /*epi_conv=*/0);
}

// round 17
// speedup vs baseline: 1.0014x; 1.0014x over previous
#include <cuda_runtime.h>
#include <math.h>

#define NN 100000
#define EE 1600000
#define DD 128
#define NB 391   // ceil(NN/256)

// ---- scratch (allocation-free: device globals) ----
__device__ __align__(16) int   g_deg[NN];
__device__ __align__(16) int   g_cursor[NN];
__device__ __align__(16) int   g_rowstart[NN];
__device__ __align__(16) int   g_bsum[512];
__device__ __align__(16) int   g_boff[512];
__device__ int                 g_w64;               // 1 if edge_index is int64
__device__ __align__(16) float g_dis[NN];
__device__ __align__(16) int2  g_epack[EE];         // {src, coef bits}
__device__ __align__(16) float g_xw [(size_t)NN * DD];
__device__ __align__(16) float g_agg[(size_t)NN * DD];

// ---------------------------------------------------------------------------
// dtype probe: if edge_index is int64 (little-endian, values < 2^31), every
// odd 32-bit word is 0. If int32, odd words are node ids (~all nonzero).
// ---------------------------------------------------------------------------
__global__ void k_detect(const int* __restrict__ ei32) {
    __shared__ int nz;
    if (threadIdx.x == 0) nz = 0;
    __syncthreads();
    for (int i = threadIdx.x; i < 4096; i += 256)
        if (ei32[2 * i + 1] != 0) atomicOr(&nz, 1);
    __syncthreads();
    if (threadIdx.x == 0) g_w64 = (nz == 0) ? 1 : 0;
}

// ---------------------------------------------------------------------------
// degree / normalization / CSR build (index loads are dtype-agnostic)
// ---------------------------------------------------------------------------
__global__ void k_zero() {
    int i = blockIdx.x * blockDim.x + threadIdx.x;
    if (i < NN) { g_deg[i] = 0; g_cursor[i] = 0; }
}

__global__ void k_deg(const int* __restrict__ ei32) {
    int e = blockIdx.x * blockDim.x + threadIdx.x;
    if (e >= EE) return;
    int w64 = g_w64;
    size_t di = w64 ? (2 * (size_t)EE + 2 * (size_t)e) : ((size_t)EE + e);
    unsigned d = (unsigned)ei32[di];
    if (d < NN) atomicAdd(&g_deg[d], 1);
}

__global__ void k_dis() {
    int i = blockIdx.x * blockDim.x + threadIdx.x;
    if (i < NN) g_dis[i] = rsqrtf((float)g_deg[i] + 1.0f);
}

// pass 1: per-block inclusive scan -> exclusive rowstart (partial) + block sums
__global__ __launch_bounds__(256) void k_scan1() {
    __shared__ int s[256];
    int t = threadIdx.x, b = blockIdx.x;
    int i = b * 256 + t;
    int v = (i < NN) ? g_deg[i] : 0;
    s[t] = v; __syncthreads();
#pragma unroll
    for (int off = 1; off < 256; off <<= 1) {
        int x = 0;
        if (t >= off) x = s[t - off];
        __syncthreads();
        s[t] += x;
        __syncthreads();
    }
    if (i < NN) g_rowstart[i] = s[t] - v;
    if (t == 255) g_bsum[b] = s[255];
}

// pass 2: single block scans the NB block sums (exclusive)
__global__ __launch_bounds__(512) void k_scan2() {
    __shared__ int s[512];
    int t = threadIdx.x;
    int v = (t < NB) ? g_bsum[t] : 0;
    s[t] = v; __syncthreads();
#pragma unroll
    for (int off = 1; off < 512; off <<= 1) {
        int x = 0;
        if (t >= off) x = s[t - off];
        __syncthreads();
        s[t] += x;
        __syncthreads();
    }
    if (t < NB) g_boff[t] = s[t] - v;
}

// pass 3: add block offsets
__global__ __launch_bounds__(256) void k_scan3() {
    int i = blockIdx.x * 256 + threadIdx.x;
    if (i < NN) g_rowstart[i] += g_boff[blockIdx.x];
}

// bucket edges by dst: epack[slot] = {src, bits(dis[src]*dis[dst])}
__global__ void k_bucket(const int* __restrict__ ei32) {
    int e = blockIdx.x * blockDim.x + threadIdx.x;
    if (e >= EE) return;
    int w64 = g_w64;
    size_t si = w64 ? (2 * (size_t)e) : (size_t)e;
    size_t di = w64 ? (2 * (size_t)EE + 2 * (size_t)e) : ((size_t)EE + e);
    unsigned s = (unsigned)ei32[si];
    unsigned d = (unsigned)ei32[di];
    if (s >= NN || d >= NN) return;                 // clamp: drop bad edge
    int pos = g_rowstart[d] + atomicAdd(&g_cursor[d], 1);
    if ((unsigned)pos >= EE) return;                // clamp: cannot fault
    int2 q;
    q.x = (int)s;
    q.y = __float_as_int(g_dis[s] * g_dis[d]);
    g_epack[pos] = q;
}

// ---------------------------------------------------------------------------
// GEMM: C[64 x 128] tile per block, K=128 in 4 chunks of 32.
// epi_conv == 1: out_xw = A@W ; out_agg = dis^2 * (A@W) + bias   (pre-gather)
// epi_conv == 0: out_xw = relu(A@W + bias)                        (projections)
// relu_in  == 1: relu applied to A on load (fuses layer-1 activation)
// ---------------------------------------------------------------------------
__global__ __launch_bounds__(256) void k_gemm(
    const float* __restrict__ A, const float* __restrict__ W,
    const float* __restrict__ bias,
    float* __restrict__ out_xw, float* __restrict__ out_agg,
    int relu_in, int epi_conv)
{
    __shared__ float4 As[64 * 8];   // 64 rows x 32 k
    __shared__ float4 Ws[32 * 32];  // 32 k x 128 cols

    const int tid = threadIdx.x;
    const int tx  = tid & 31;
    const int ty  = tid >> 5;
    const int rowBase = blockIdx.x * 64;

    const float4* A4 = (const float4*)A;
    const float4* W4 = (const float4*)W;

    float4 acc[8];
#pragma unroll
    for (int i = 0; i < 8; i++) acc[i] = make_float4(0.f, 0.f, 0.f, 0.f);

    for (int kc = 0; kc < DD; kc += 32) {
        for (int t = tid; t < 64 * 8; t += 256) {
            int r = t >> 3, c = t & 7;
            int rg = rowBase + r;
            float4 v = make_float4(0.f, 0.f, 0.f, 0.f);
            if (rg < NN) v = A4[(size_t)rg * 32 + (kc >> 2) + c];
            if (relu_in) {
                v.x = fmaxf(v.x, 0.f); v.y = fmaxf(v.y, 0.f);
                v.z = fmaxf(v.z, 0.f); v.w = fmaxf(v.w, 0.f);
            }
            As[t] = v;
        }
        for (int t = tid; t < 32 * 32; t += 256) {
            int k = t >> 5, c = t & 31;
            Ws[t] = W4[(size_t)(kc + k) * 32 + c];
        }
        __syncthreads();

#pragma unroll
        for (int k4 = 0; k4 < 8; k4++) {
            float4 b0 = Ws[(k4 * 4 + 0) * 32 + tx];
            float4 b1 = Ws[(k4 * 4 + 1) * 32 + tx];
            float4 b2 = Ws[(k4 * 4 + 2) * 32 + tx];
            float4 b3 = Ws[(k4 * 4 + 3) * 32 + tx];
#pragma unroll
            for (int i = 0; i < 8; i++) {
                float4 a = As[(ty * 8 + i) * 8 + k4];
                acc[i].x = fmaf(a.x, b0.x, acc[i].x);
                acc[i].x = fmaf(a.y, b1.x, acc[i].x);
                acc[i].x = fmaf(a.z, b2.x, acc[i].x);
                acc[i].x = fmaf(a.w, b3.x, acc[i].x);
                acc[i].y = fmaf(a.x, b0.y, acc[i].y);
                acc[i].y = fmaf(a.y, b1.y, acc[i].y);
                acc[i].y = fmaf(a.z, b2.y, acc[i].y);
                acc[i].y = fmaf(a.w, b3.y, acc[i].y);
                acc[i].z = fmaf(a.x, b0.z, acc[i].z);
                acc[i].z = fmaf(a.y, b1.z, acc[i].z);
                acc[i].z = fmaf(a.z, b2.z, acc[i].z);
                acc[i].z = fmaf(a.w, b3.z, acc[i].z);
                acc[i].w = fmaf(a.x, b0.w, acc[i].w);
                acc[i].w = fmaf(a.y, b1.w, acc[i].w);
                acc[i].w = fmaf(a.z, b2.w, acc[i].w);
                acc[i].w = fmaf(a.w, b3.w, acc[i].w);
            }
        }
        __syncthreads();
    }

    const float4 bv = ((const float4*)bias)[tx];
#pragma unroll
    for (int i = 0; i < 8; i++) {
        int rg = rowBase + ty * 8 + i;
        if (rg >= NN) continue;
        float4 o = acc[i];
        if (epi_conv) {
            ((float4*)out_xw)[(size_t)rg * 32 + tx] = o;
            float d = g_dis[rg];
            float d2 = d * d;
            float4 g;
            g.x = fmaf(o.x, d2, bv.x);
            g.y = fmaf(o.y, d2, bv.y);
            g.z = fmaf(o.z, d2, bv.z);
            g.w = fmaf(o.w, d2, bv.w);
            ((float4*)out_agg)[(size_t)rg * 32 + tx] = g;
        } else {
            float4 g;
            g.x = fmaxf(o.x + bv.x, 0.f);
            g.y = fmaxf(o.y + bv.y, 0.f);
            g.z = fmaxf(o.z + bv.z, 0.f);
            g.w = fmaxf(o.w + bv.w, 0.f);
            ((float4*)out_xw)[(size_t)rg * 32 + tx] = g;
        }
    }
}

// ---------------------------------------------------------------------------
// CSR gather: one warp per dst node, lane owns one float4 column chunk.
// acc starts from agg[dst] (= dis^2*xw + b from GEMM epilogue); no atomics.
// ---------------------------------------------------------------------------
__global__ __launch_bounds__(256) void k_gather(
    const float* __restrict__ xw, float* __restrict__ agg)
{
    int node = blockIdx.x * 8 + (threadIdx.x >> 5);
    int lane = threadIdx.x & 31;
    if (node >= NN) return;

    int start = g_rowstart[node];
    int cnt   = g_deg[node];
    start = max(0, min(start, EE));                 // clamp: cannot fault
    cnt   = max(0, min(cnt, EE - start));

    const int2*   ep  = g_epack + start;
    const float4* xw4 = (const float4*)xw;

    float4 acc = ((const float4*)agg)[(size_t)node * 32 + lane];

    int j = 0;
    for (; j + 4 <= cnt; j += 4) {
        int2 p0 = ep[j + 0];
        int2 p1 = ep[j + 1];
        int2 p2 = ep[j + 2];
        int2 p3 = ep[j + 3];
        int s0 = min(max(p0.x, 0), NN - 1);
        int s1 = min(max(p1.x, 0), NN - 1);
        int s2 = min(max(p2.x, 0), NN - 1);
        int s3 = min(max(p3.x, 0), NN - 1);
        float c0 = __int_as_float(p0.y);
        float c1 = __int_as_float(p1.y);
        float c2 = __int_as_float(p2.y);
        float c3 = __int_as_float(p3.y);
        float4 v0 = xw4[(size_t)s0 * 32 + lane];
        float4 v1 = xw4[(size_t)s1 * 32 + lane];
        float4 v2 = xw4[(size_t)s2 * 32 + lane];
        float4 v3 = xw4[(size_t)s3 * 32 + lane];
        acc.x = fmaf(c0, v0.x, acc.x); acc.y = fmaf(c0, v0.y, acc.y);
        acc.z = fmaf(c0, v0.z, acc.z); acc.w = fmaf(c0, v0.w, acc.w);
        acc.x = fmaf(c1, v1.x, acc.x); acc.y = fmaf(c1, v1.y, acc.y);
        acc.z = fmaf(c1, v1.z, acc.z); acc.w = fmaf(c1, v1.w, acc.w);
        acc.x = fmaf(c2, v2.x, acc.x); acc.y = fmaf(c2, v2.y, acc.y);
        acc.z = fmaf(c2, v2.z, acc.z); acc.w = fmaf(c2, v2.w, acc.w);
        acc.x = fmaf(c3, v3.x, acc.x); acc.y = fmaf(c3, v3.y, acc.y);
        acc.z = fmaf(c3, v3.z, acc.z); acc.w = fmaf(c3, v3.w, acc.w);
    }
    for (; j < cnt; j++) {
        int2 p = ep[j];
        int sj = min(max(p.x, 0), NN - 1);
        float cj = __int_as_float(p.y);
        float4 v = xw4[(size_t)sj * 32 + lane];
        acc.x = fmaf(cj, v.x, acc.x); acc.y = fmaf(cj, v.y, acc.y);
        acc.z = fmaf(cj, v.z, acc.z); acc.w = fmaf(cj, v.w, acc.w);
    }

    ((float4*)agg)[(size_t)node * 32 + lane] = acc;
}

// ---------------------------------------------------------------------------
extern "C" void kernel_launch(void* const* d_in, const int* in_sizes, int n_in,
                              void* d_out, int out_size)
{
    // --- size-based input resolution (robust to ordering surprises) ---
    const float* x  = nullptr;
    const int*   ei = nullptr;    // edge_index as raw 32-bit words
    const float* mats[4] = {nullptr, nullptr, nullptr, nullptr};
    const float* vecs[4] = {nullptr, nullptr, nullptr, nullptr};
    int nm = 0, nv = 0;
    for (int i = 0; i < n_in; i++) {
        int sz = in_sizes[i];
        if (sz == NN * DD)            x  = (const float*)d_in[i];
        else if (sz == 2 * EE)        ei = (const int*)d_in[i];
        else if (sz == DD * DD) { if (nm < 4) mats[nm++] = (const float*)d_in[i]; }
        else if (sz == DD)      { if (nv < 4) vecs[nv++] = (const float*)d_in[i]; }
    }
    if (!x)  x  = (const float*)d_in[0];
    if (!ei) ei = (const int*)d_in[1];
    if (nm < 4) { mats[0]=(const float*)d_in[2]; mats[1]=(const float*)d_in[4];
                  mats[2]=(const float*)d_in[6]; mats[3]=(const float*)d_in[8]; }
    if (nv < 4) { vecs[0]=(const float*)d_in[3]; vecs[1]=(const float*)d_in[5];
                  vecs[2]=(const float*)d_in[7]; vecs[3]=(const float*)d_in[9]; }
    const float *W1 = mats[0], *W2 = mats[1], *Wv = mats[2], *Wt = mats[3];
    const float *b1 = vecs[0], *b2 = vecs[1], *bv = vecs[2], *bt = vecs[3];

    float* out = (float*)d_out;
    float* h  = out;                       // [N, D]
    float* xv = out + (size_t)NN * DD;     // [N, D]
    float* xt = out + 2 * (size_t)NN * DD; // [N, D]

    float* xw  = nullptr;
    float* agg = nullptr;
    cudaGetSymbolAddress((void**)&xw,  g_xw);
    cudaGetSymbolAddress((void**)&agg, g_agg);

    const int TPB = 256;
    dim3 gN((NN + TPB - 1) / TPB);    // == NB blocks
    dim3 gE((EE + TPB - 1) / TPB);
    dim3 gG((NN + 63) / 64);
    dim3 gW((NN + 7) / 8);            // gather: 8 warps/block, warp per node

    // dtype probe + normalization + CSR build
    k_detect<<<1, 256>>>(ei);
    k_zero <<<gN, TPB>>>();
    k_deg  <<<gE, TPB>>>(ei);
    k_scan1<<<gN, TPB>>>();
    k_scan2<<<1, 512>>>();
    k_scan3<<<gN, TPB>>>();
    k_dis  <<<gN, TPB>>>();
    k_bucket<<<gE, TPB>>>(ei);

    // layer 1: xw = x@W1 ; agg = dis^2*xw + b1 ; gather adds neighbors
    k_gemm  <<<gG, TPB>>>(x, W1, b1, xw, agg, /*relu_in=*/0, /*epi_conv=*/1);
    k_gather<<<gW, TPB>>>(xw, agg);

    // layer 2: reads relu(agg1) fused on load; agg target is d_out h region
    k_gemm  <<<gG, TPB>>>(agg, W2, b2, xw, h, /*relu_in=*/1, /*epi_conv=*/1);
    k_gather<<<gW, TPB>>>(xw, h);

    // output projections
    k_gemm<<<gG, TPB>>>(h, Wv, bv, xv, nullptr, /*relu_in=*/0, /*epi_conv=*/0);
    k_gemm<<<gG, TPB>>>(h, Wt, bt, xt, nullptr, /*relu_in=*/0, /*epi_conv=*/0);
}